// round 1
// baseline (speedup 1.0000x reference)
#include <cuda_runtime.h>

// Correlation cost volume: out[b, dy*9+dx, y, x] = (1/C) * sum_c in1[b,c,y,x] * in2pad[b,c,y+dy-4,x+dx-4]
// B=8, C=128, H=96, W=128, d=4 -> 81 displacements.

#define B_   8
#define C_   128
#define H_   96
#define W_   128
#define ND   9        // 2*d+1
#define CC   16       // channels per smem chunk
#define TY   8        // tile rows per block
#define TX   32       // tile cols per block
#define S2H  (TY + 8) // 16: in2 tile rows (halo)
#define S2W  (TX + 8) // 40: in2 tile cols (halo)
#define NTHR 64       // 8 rows x 8 quads (each thread owns 4 consecutive x)

// smem: s1[CC][TY][TX] + s2[CC][S2H][S2W]  = 16KB + 40KB = 56KB
#define S1_FLOATS (CC * TY * TX)     // 4096
#define S2_FLOATS (CC * S2H * S2W)   // 10240
#define SMEM_BYTES ((S1_FLOATS + S2_FLOATS) * 4)  // 57344

__global__ __launch_bounds__(NTHR) void corr_kernel(
    const float* __restrict__ in1,
    const float* __restrict__ in2,
    float* __restrict__ out)
{
    extern __shared__ float smem[];
    float* __restrict__ s1 = smem;              // [CC][TY][TX]
    float* __restrict__ s2 = smem + S1_FLOATS;  // [CC][S2H][S2W]

    const int t  = threadIdx.x;
    const int x0 = blockIdx.x * TX;
    const int y0 = blockIdx.y * TY;
    const int b  = blockIdx.z;

    const int r = t >> 3;  // 0..7  (row within tile)
    const int q = t & 7;   // 0..7  (quad of 4 x-pixels)

    const float scale = 1.0f / (float)C_;

    for (int c0 = 0; c0 < C_; c0 += CC) {
        // ---- fill s1: 1024 float4, 16 per thread, coalesced ----
        #pragma unroll
        for (int k = 0; k < 16; ++k) {
            const int i   = t + k * NTHR;
            const int c   = i >> 6;        // /64
            const int rem = i & 63;
            const int rr  = rem >> 3;
            const int qq  = rem & 7;
            const float4 v = *(const float4*)&in1[
                (((b * C_ + c0 + c) * H_ + y0 + rr) * W_ + x0) + qq * 4];
            *(float4*)&s1[(c * TY + rr) * TX + qq * 4] = v;
        }

        // ---- fill s2: 256 rows x 10 float4 = 2560 float4, 40 per thread ----
        #pragma unroll 8
        for (int k = 0; k < 40; ++k) {
            const int i   = t + k * NTHR;
            const int row = i / 10;            // 0..255  (c*16 + r2)
            const int j4  = i - row * 10;      // 0..9
            const int c   = row >> 4;
            const int r2  = row & 15;
            const int gy  = y0 + r2 - 4;
            const int gx  = x0 + j4 * 4 - 4;   // multiple of 4 -> whole-vector predicate
            float4 v = make_float4(0.f, 0.f, 0.f, 0.f);
            if (gy >= 0 && gy < H_ && gx >= 0 && gx <= W_ - 4) {
                v = *(const float4*)&in2[((b * C_ + c0 + c) * H_ + gy) * W_ + gx];
            }
            *(float4*)&s2[row * S2W + j4 * 4] = v;
        }
        __syncthreads();

        // ---- compute: for each dy, accumulate 9dx x 4px over CC channels ----
        for (int dy = 0; dy < ND; ++dy) {
            float4 acc[ND];
            #pragma unroll
            for (int dx = 0; dx < ND; ++dx) acc[dx] = make_float4(0.f, 0.f, 0.f, 0.f);

            #pragma unroll 4
            for (int c = 0; c < CC; ++c) {
                const float4 a = *(const float4*)&s1[(c * TY + r) * TX + q * 4];
                const float* wr = &s2[(c * S2H + r + dy) * S2W + q * 4];
                const float4 w0 = *(const float4*)(wr);
                const float4 w1 = *(const float4*)(wr + 4);
                const float4 w2 = *(const float4*)(wr + 8);
                const float w[12] = { w0.x, w0.y, w0.z, w0.w,
                                      w1.x, w1.y, w1.z, w1.w,
                                      w2.x, w2.y, w2.z, w2.w };
                #pragma unroll
                for (int dx = 0; dx < ND; ++dx) {
                    acc[dx].x = fmaf(a.x, w[dx + 0], acc[dx].x);
                    acc[dx].y = fmaf(a.y, w[dx + 1], acc[dx].y);
                    acc[dx].z = fmaf(a.z, w[dx + 2], acc[dx].z);
                    acc[dx].w = fmaf(a.w, w[dx + 3], acc[dx].w);
                }
            }

            // ---- accumulate partial sums into out (block-private, no races) ----
            #pragma unroll
            for (int dx = 0; dx < ND; ++dx) {
                float4* o = (float4*)&out[
                    (((b * 81 + dy * ND + dx) * H_) + y0 + r) * W_ + x0 + q * 4];
                float4 v;
                if (c0 == 0) {
                    v = make_float4(0.f, 0.f, 0.f, 0.f);  // overwrite poison
                } else {
                    v = *o;
                }
                v.x += acc[dx].x * scale;
                v.y += acc[dx].y * scale;
                v.z += acc[dx].z * scale;
                v.w += acc[dx].w * scale;
                *o = v;
            }
        }
        __syncthreads();  // protect smem before next chunk's fill
    }
}

extern "C" void kernel_launch(void* const* d_in, const int* in_sizes, int n_in,
                              void* d_out, int out_size)
{
    const float* in1 = (const float*)d_in[0];
    const float* in2 = (const float*)d_in[1];
    float* out = (float*)d_out;

    cudaFuncSetAttribute(corr_kernel,
                         cudaFuncAttributeMaxDynamicSharedMemorySize, SMEM_BYTES);

    dim3 grid(W_ / TX, H_ / TY, B_);  // (4, 12, 8) = 384 blocks
    dim3 block(NTHR);
    corr_kernel<<<grid, block, SMEM_BYTES>>>(in1, in2, out);
}

// round 2
// speedup vs baseline: 1.3560x; 1.3560x over previous
#include <cuda_runtime.h>

// Correlation cost volume: out[b, dy*9+dx, y, x] = (1/C) * sum_c in1[b,c,y,x] * in2pad[b,c,y+dy-4,x+dx-4]
// B=8, C=128, H=96, W=128, d=4 -> 81 displacements.
//
// Round 2: dy parallelized across threads (3 dy-groups/block of 64 threads) and
// blocks (grid.z = B*3). Accumulators persist across the channel loop -> single
// final STG, no out RMW. Smaller smem halo per block (10 rows instead of 16).

#define B_   8
#define C_   128
#define H_   96
#define W_   128
#define ND   9          // 2*d+1
#define CC   16         // channels per smem chunk
#define TY   8          // tile rows per block
#define TX   32         // tile cols per block
#define S2H  10         // in2 tile rows needed for 3 consecutive dy (8 + 2 halo)
#define S2W  (TX + 8)   // 40: in2 tile cols (halo)
#define NTHR 192        // 3 dy-groups x 64 threads

#define S1_FLOATS (CC * TY * TX)     // 4096  (16 KB)
#define S2_FLOATS (CC * S2H * S2W)   // 6400  (25.6 KB)
#define SMEM_BYTES ((S1_FLOATS + S2_FLOATS) * 4)  // 41984

__global__ __launch_bounds__(NTHR) void corr_kernel(
    const float* __restrict__ in1,
    const float* __restrict__ in2,
    float* __restrict__ out)
{
    extern __shared__ float smem[];
    float* __restrict__ s1 = smem;              // [CC][TY][TX]
    float* __restrict__ s2 = smem + S1_FLOATS;  // [CC][S2H][S2W]

    const int t   = threadIdx.x;
    const int x0  = blockIdx.x * TX;
    const int y0  = blockIdx.y * TY;
    const int b   = blockIdx.z / 3;
    const int dyg = blockIdx.z % 3;     // dy group: covers dy = 3*dyg + {0,1,2}

    const int tg = t & 63;
    const int r  = tg >> 3;             // 0..7  row within tile
    const int q  = tg & 7;              // 0..7  quad of 4 x-pixels
    const int g  = t >> 6;              // 0..2  dy within group
    const int dy = dyg * 3 + g;

    // s2 covers global rows [ybase, ybase+9]; access row for (r, g) is r+g.
    const int ybase = y0 + dyg * 3 - 4;

    float4 acc[ND];
    #pragma unroll
    for (int dx = 0; dx < ND; ++dx) acc[dx] = make_float4(0.f, 0.f, 0.f, 0.f);

    for (int c0 = 0; c0 < C_; c0 += CC) {
        // ---- fill s1: 1024 float4, coalesced ----
        for (int i = t; i < S1_FLOATS / 4; i += NTHR) {
            const int c   = i >> 6;      // /64
            const int rem = i & 63;
            const int rr  = rem >> 3;
            const int qq  = rem & 7;
            const float4 v = *(const float4*)&in1[
                (((b * C_ + c0 + c) * H_ + y0 + rr) * W_ + x0) + qq * 4];
            *(float4*)&s1[(c * TY + rr) * TX + qq * 4] = v;
        }

        // ---- fill s2: 160 rows x 10 float4 = 1600 float4 ----
        for (int i = t; i < S2_FLOATS / 4; i += NTHR) {
            const int row = i / 10;            // 0..159  (c*10 + r2)
            const int j4  = i - row * 10;      // 0..9
            const int c   = row / 10;
            const int r2  = row - c * 10;
            const int gy  = ybase + r2;
            const int gx  = x0 + j4 * 4 - 4;   // multiple of 4 -> whole-vector predicate
            float4 v = make_float4(0.f, 0.f, 0.f, 0.f);
            if (gy >= 0 && gy < H_ && gx >= 0 && gx <= W_ - 4) {
                v = *(const float4*)&in2[((b * C_ + c0 + c) * H_ + gy) * W_ + gx];
            }
            *(float4*)&s2[row * S2W + j4 * 4] = v;
        }
        __syncthreads();

        // ---- accumulate this chunk: 16 channels x 9 dx x 4 px FMAs ----
        #pragma unroll 4
        for (int c = 0; c < CC; ++c) {
            const float4 a = *(const float4*)&s1[(c * TY + r) * TX + q * 4];
            const float* wr = &s2[(c * S2H + r + g) * S2W + q * 4];
            const float4 w0 = *(const float4*)(wr);
            const float4 w1 = *(const float4*)(wr + 4);
            const float4 w2 = *(const float4*)(wr + 8);
            const float w[12] = { w0.x, w0.y, w0.z, w0.w,
                                  w1.x, w1.y, w1.z, w1.w,
                                  w2.x, w2.y, w2.z, w2.w };
            #pragma unroll
            for (int dx = 0; dx < ND; ++dx) {
                acc[dx].x = fmaf(a.x, w[dx + 0], acc[dx].x);
                acc[dx].y = fmaf(a.y, w[dx + 1], acc[dx].y);
                acc[dx].z = fmaf(a.z, w[dx + 2], acc[dx].z);
                acc[dx].w = fmaf(a.w, w[dx + 3], acc[dx].w);
            }
        }
        __syncthreads();   // protect smem before next chunk's fill
    }

    // ---- single final store (overwrites harness poison) ----
    const float scale = 1.0f / (float)C_;
    #pragma unroll
    for (int dx = 0; dx < ND; ++dx) {
        float4 v;
        v.x = acc[dx].x * scale;
        v.y = acc[dx].y * scale;
        v.z = acc[dx].z * scale;
        v.w = acc[dx].w * scale;
        *(float4*)&out[(((b * 81 + dy * ND + dx) * H_) + y0 + r) * W_ + x0 + q * 4] = v;
    }
}

extern "C" void kernel_launch(void* const* d_in, const int* in_sizes, int n_in,
                              void* d_out, int out_size)
{
    const float* in1 = (const float*)d_in[0];
    const float* in2 = (const float*)d_in[1];
    float* out = (float*)d_out;

    cudaFuncSetAttribute(corr_kernel,
                         cudaFuncAttributeMaxDynamicSharedMemorySize, SMEM_BYTES);

    dim3 grid(W_ / TX, H_ / TY, B_ * 3);  // (4, 12, 24) = 1152 blocks
    dim3 block(NTHR);
    corr_kernel<<<grid, block, SMEM_BYTES>>>(in1, in2, out);
}